// round 9
// baseline (speedup 1.0000x reference)
#include <cuda_runtime.h>
#include <cuda_bf16.h>
#include <cstdint>

// GridSpatialIntegral: input [B=64, C=2, WY=512, WX=512] fp32.
//   out[:,0,:,:] = cumsum over x of in[:,0,:,:]
//   out[:,1,:,:] = cumsum over y of in[:,1,:,:]
//
// Single fused kernel, 512-thread blocks:
//   blocks [0, 1024)        : channel-1. Block owns 32 cols x 512 rows.
//                             Whole 64 KB tile staged to dynamic smem with
//                             cp.async.cg (MLP without register cost), then
//                             16 warps scan 32-row segments from smem.
//   blocks [1024, 3072)     : channel-0 row scans — verbatim R5 path
//                             (warp per row, lane-contiguous float4).

#define B   64
#define WY  512
#define WX  512

#define CH1_BLOCKS 1024                // 32768 columns / 32 per block
#define CH0_BLOCKS 2048                // 32768 rows / 16 warps-per-block
#define TOTAL_BLOCKS (CH1_BLOCKS + CH0_BLOCKS)
#define THREADS 512

#define CH1_SMEM_BYTES (WY * 32 * 4)   // 512 rows x 32 cols fp32 = 64 KB

__device__ __forceinline__ float warp_incl_scan(float v, int lane) {
    #pragma unroll
    for (int d = 1; d < 32; d <<= 1) {
        float n = __shfl_up_sync(0xffffffffu, v, d);
        if (lane >= d) v += n;
    }
    return v;
}

__global__ __launch_bounds__(THREADS)
void grid_spatial_integral_kernel(const float* __restrict__ in,
                                  float* __restrict__ out) {
    const int bx = blockIdx.x;
    __shared__ float seg_totals[16][32];
    extern __shared__ float tile[];    // [512][32] for ch1 blocks

    if (bx < CH1_BLOCKS) {
        // ---------------- Channel 1: cumsum along y ----------------
        const int lane = threadIdx.x & 31;
        const int seg  = threadIdx.x >> 5;          // 0..15
        const int b    = bx >> 4;                   // 16 col-groups per batch
        const int xg   = bx & 15;

        // ---- stage full tile to smem via cp.async (16B per op) ----
        {
            const int colg  = threadIdx.x & 7;      // 16B group within 32 cols
            const int rbase = threadIdx.x >> 3;     // 0..63
            const float* gsrc = in + ((size_t)(b * 2 + 1) * WY) * WX
                                   + xg * 32 + colg * 4;
            uint32_t sdst = (uint32_t)__cvta_generic_to_shared(tile)
                            + (uint32_t)rbase * 128 + (uint32_t)colg * 16;
            #pragma unroll
            for (int s = 0; s < 8; ++s) {
                const int r = s * 64 + rbase;
                asm volatile("cp.async.cg.shared.global [%0], [%1], 16;"
                             :: "r"(sdst + (uint32_t)s * 64 * 128),
                                "l"(gsrc + (size_t)r * WX)
                             : "memory");
            }
            asm volatile("cp.async.commit_group;" ::: "memory");
            asm volatile("cp.async.wait_group 0;" ::: "memory");
        }
        __syncthreads();

        // ---- pass 1: segment totals (warp seg owns rows [32seg, 32seg+32)) ----
        const float* my = tile + (seg * 32) * 32 + lane;   // row stride 32 floats
        float total = 0.0f;
        #pragma unroll
        for (int k = 0; k < 32; ++k)
            total += my[k * 32];

        seg_totals[seg][lane] = total;
        __syncthreads();

        float carry = 0.0f;
        #pragma unroll
        for (int s = 0; s < 15; ++s)
            if (s < seg) carry += seg_totals[s][lane];

        // ---- pass 2: prefix + store ----
        float* q = out + ((size_t)(b * 2 + 1) * WY + seg * 32) * WX
                       + xg * 32 + lane;
        float acc = carry;
        #pragma unroll
        for (int k = 0; k < 32; ++k) {
            acc += my[k * 32];
            __stcs(q + k * WX, acc);
        }
    } else {
        // ---------------- Channel 0: cumsum along x (R5 verbatim) ----------
        const int idx  = bx - CH1_BLOCKS;           // 0..2047
        const int wid  = threadIdx.x >> 5;          // 0..15
        const int lane = threadIdx.x & 31;
        const int row  = idx * 16 + wid;            // 0..32767
        const int b    = row >> 9;
        const int y    = row & 511;

        const int base = ((b * 2 + 0) * WY + y) * WX;
        const float4* __restrict__ src = (const float4*)(in  + base);
        float4*       __restrict__ dst = (float4*)(out + base);

        float4 a0 = __ldcs(src + 0 * 32 + lane);
        float4 a1 = __ldcs(src + 1 * 32 + lane);
        float4 a2 = __ldcs(src + 2 * 32 + lane);
        float4 a3 = __ldcs(src + 3 * 32 + lane);

        a0.y += a0.x; a0.z += a0.y; a0.w += a0.z;
        a1.y += a1.x; a1.z += a1.y; a1.w += a1.z;
        a2.y += a2.x; a2.z += a2.y; a2.w += a2.z;
        a3.y += a3.x; a3.z += a3.y; a3.w += a3.z;

        const float t0 = a0.w, t1 = a1.w, t2 = a2.w, t3 = a3.w;
        float i0 = warp_incl_scan(t0, lane);
        float i1 = warp_incl_scan(t1, lane);
        float i2 = warp_incl_scan(t2, lane);
        float i3 = warp_incl_scan(t3, lane);
        const float T0 = __shfl_sync(0xffffffffu, i0, 31);
        const float T1 = __shfl_sync(0xffffffffu, i1, 31);
        const float T2 = __shfl_sync(0xffffffffu, i2, 31);

        const float o0 = i0 - t0;
        const float o1 = (i1 - t1) + T0;
        const float o2 = (i2 - t2) + T0 + T1;
        const float o3 = (i3 - t3) + T0 + T1 + T2;

        a0.x += o0; a0.y += o0; a0.z += o0; a0.w += o0;
        a1.x += o1; a1.y += o1; a1.z += o1; a1.w += o1;
        a2.x += o2; a2.y += o2; a2.z += o2; a2.w += o2;
        a3.x += o3; a3.y += o3; a3.z += o3; a3.w += o3;

        __stcs(dst + 0 * 32 + lane, a0);
        __stcs(dst + 1 * 32 + lane, a1);
        __stcs(dst + 2 * 32 + lane, a2);
        __stcs(dst + 3 * 32 + lane, a3);
    }
}

extern "C" void kernel_launch(void* const* d_in, const int* in_sizes, int n_in,
                              void* d_out, int out_size) {
    const float* in  = (const float*)d_in[0];
    float*       out = (float*)d_out;
    cudaFuncSetAttribute(grid_spatial_integral_kernel,
                         cudaFuncAttributeMaxDynamicSharedMemorySize,
                         CH1_SMEM_BYTES);
    grid_spatial_integral_kernel<<<TOTAL_BLOCKS, THREADS, CH1_SMEM_BYTES>>>(in, out);
}

// round 10
// speedup vs baseline: 1.0629x; 1.0629x over previous
#include <cuda_runtime.h>
#include <cuda_bf16.h>

// GridSpatialIntegral: input [B=64, C=2, WY=512, WX=512] fp32.
//   out[:,0,:,:] = cumsum over x of in[:,0,:,:]
//   out[:,1,:,:] = cumsum over y of in[:,1,:,:]
//
// Champion configuration (R5): single fused kernel, 512-thread blocks,
// __launch_bounds__(512, 2)  <-- load-bearing: holds regs at 48, 2 blocks/SM.
//   blocks [0, 1024)        : channel-1. Block owns 32 columns x 512 rows.
//                             16 warps; warp w owns 32-row segment w; segment
//                             totals exchanged through smem.
//   blocks [1024, 1024+2048): channel-0 row scans (warp per row, 16 rows/blk),
//                             lane-contiguous float4 loads.

#define B   64
#define WY  512
#define WX  512

#define CH1_BLOCKS 1024                // 32768 columns / 32 per block
#define CH0_BLOCKS 2048                // 32768 rows / 16 warps-per-block
#define TOTAL_BLOCKS (CH1_BLOCKS + CH0_BLOCKS)
#define THREADS 512

__device__ __forceinline__ float warp_incl_scan(float v, int lane) {
    #pragma unroll
    for (int d = 1; d < 32; d <<= 1) {
        float n = __shfl_up_sync(0xffffffffu, v, d);
        if (lane >= d) v += n;
    }
    return v;
}

__global__ __launch_bounds__(THREADS, 2)
void grid_spatial_integral_kernel(const float* __restrict__ in,
                                  float* __restrict__ out) {
    const int bx = blockIdx.x;
    __shared__ float seg_totals[16][32];

    if (bx < CH1_BLOCKS) {
        // ---------------- Channel 1: cumsum along y ----------------
        // block -> (batch, 32-column group). warp -> 32-row segment.
        const int lane = threadIdx.x & 31;
        const int seg  = threadIdx.x >> 5;          // 0..15
        const int b    = bx >> 4;                   // 16 col-groups per batch
        const int xg   = bx & 15;
        const int x    = xg * 32 + lane;            // 0..511

        const int base = ((b * 2 + 1) * WY + seg * 32) * WX + x;
        const float* __restrict__ p = in  + base;
        float*       __restrict__ q = out + base;

        // load 32 rows into registers (coalesced 128B per warp instruction)
        float v[32];
        #pragma unroll
        for (int k = 0; k < 32; ++k)
            v[k] = __ldcs(p + k * WX);

        // in-register inclusive prefix over this segment
        #pragma unroll
        for (int k = 1; k < 32; ++k)
            v[k] += v[k - 1];

        // publish segment total, gather carry from lower segments
        seg_totals[seg][lane] = v[31];
        __syncthreads();

        float carry = 0.0f;
        #pragma unroll
        for (int s = 0; s < 15; ++s)
            if (s < seg) carry += seg_totals[s][lane];

        #pragma unroll
        for (int k = 0; k < 32; ++k)
            __stcs(q + k * WX, v[k] + carry);
    } else {
        // ---------------- Channel 0: cumsum along x ----------------
        // warp per 512-float row. lane-contiguous float4 loads:
        // chunk id c = i*32 + lane holds elements [4c, 4c+4).
        const int idx  = bx - CH1_BLOCKS;           // 0..2047
        const int wid  = threadIdx.x >> 5;          // 0..15
        const int lane = threadIdx.x & 31;
        const int row  = idx * 16 + wid;            // 0..32767
        const int b    = row >> 9;
        const int y    = row & 511;

        const int base = ((b * 2 + 0) * WY + y) * WX;
        const float4* __restrict__ src = (const float4*)(in  + base);
        float4*       __restrict__ dst = (float4*)(out + base);

        float4 a0 = __ldcs(src + 0 * 32 + lane);
        float4 a1 = __ldcs(src + 1 * 32 + lane);
        float4 a2 = __ldcs(src + 2 * 32 + lane);
        float4 a3 = __ldcs(src + 3 * 32 + lane);

        // inclusive scan inside each 4-element chunk
        a0.y += a0.x; a0.z += a0.y; a0.w += a0.z;
        a1.y += a1.x; a1.z += a1.y; a1.w += a1.z;
        a2.y += a2.x; a2.z += a2.y; a2.w += a2.z;
        a3.y += a3.x; a3.z += a3.y; a3.w += a3.z;

        // warp scans of chunk totals, one per chunk-row i
        const float t0 = a0.w, t1 = a1.w, t2 = a2.w, t3 = a3.w;
        float i0 = warp_incl_scan(t0, lane);
        float i1 = warp_incl_scan(t1, lane);
        float i2 = warp_incl_scan(t2, lane);
        float i3 = warp_incl_scan(t3, lane);
        const float T0 = __shfl_sync(0xffffffffu, i0, 31);
        const float T1 = __shfl_sync(0xffffffffu, i1, 31);
        const float T2 = __shfl_sync(0xffffffffu, i2, 31);

        // offset for chunk (i, lane) = sum_{j<i} T_j + excl_i(lane)
        const float o0 = i0 - t0;
        const float o1 = (i1 - t1) + T0;
        const float o2 = (i2 - t2) + T0 + T1;
        const float o3 = (i3 - t3) + T0 + T1 + T2;

        a0.x += o0; a0.y += o0; a0.z += o0; a0.w += o0;
        a1.x += o1; a1.y += o1; a1.z += o1; a1.w += o1;
        a2.x += o2; a2.y += o2; a2.z += o2; a2.w += o2;
        a3.x += o3; a3.y += o3; a3.z += o3; a3.w += o3;

        __stcs(dst + 0 * 32 + lane, a0);
        __stcs(dst + 1 * 32 + lane, a1);
        __stcs(dst + 2 * 32 + lane, a2);
        __stcs(dst + 3 * 32 + lane, a3);
    }
}

extern "C" void kernel_launch(void* const* d_in, const int* in_sizes, int n_in,
                              void* d_out, int out_size) {
    const float* in  = (const float*)d_in[0];
    float*       out = (float*)d_out;
    grid_spatial_integral_kernel<<<TOTAL_BLOCKS, THREADS>>>(in, out);
}

// round 11
// speedup vs baseline: 1.0934x; 1.0287x over previous
#include <cuda_runtime.h>
#include <cuda_bf16.h>

// GridSpatialIntegral: input [B=64, C=2, WY=512, WX=512] fp32.
//   out[:,0,:,:] = cumsum over x of in[:,0,:,:]
//   out[:,1,:,:] = cumsum over y of in[:,1,:,:]
//
// CHAMPION (R5/R10): single fused kernel, 512-thread blocks,
// __launch_bounds__(512, 2)  <-- load-bearing: holds regs at 48, 2 blocks/SM.
// Measured: ~37.5-38.2us kernel, ~7.1 TB/s effective (~89% of HBM spec).
//   blocks [0, 1024)        : channel-1. Block owns 32 columns x 512 rows.
//                             16 warps; warp w owns 32-row segment w; segment
//                             totals exchanged through smem.
//   blocks [1024, 1024+2048): channel-0 row scans (warp per row, 16 rows/blk),
//                             lane-contiguous float4 loads.

#define B   64
#define WY  512
#define WX  512

#define CH1_BLOCKS 1024                // 32768 columns / 32 per block
#define CH0_BLOCKS 2048                // 32768 rows / 16 warps-per-block
#define TOTAL_BLOCKS (CH1_BLOCKS + CH0_BLOCKS)
#define THREADS 512

__device__ __forceinline__ float warp_incl_scan(float v, int lane) {
    #pragma unroll
    for (int d = 1; d < 32; d <<= 1) {
        float n = __shfl_up_sync(0xffffffffu, v, d);
        if (lane >= d) v += n;
    }
    return v;
}

__global__ __launch_bounds__(THREADS, 2)
void grid_spatial_integral_kernel(const float* __restrict__ in,
                                  float* __restrict__ out) {
    const int bx = blockIdx.x;
    __shared__ float seg_totals[16][32];

    if (bx < CH1_BLOCKS) {
        // ---------------- Channel 1: cumsum along y ----------------
        // block -> (batch, 32-column group). warp -> 32-row segment.
        const int lane = threadIdx.x & 31;
        const int seg  = threadIdx.x >> 5;          // 0..15
        const int b    = bx >> 4;                   // 16 col-groups per batch
        const int xg   = bx & 15;
        const int x    = xg * 32 + lane;            // 0..511

        const int base = ((b * 2 + 1) * WY + seg * 32) * WX + x;
        const float* __restrict__ p = in  + base;
        float*       __restrict__ q = out + base;

        // load 32 rows into registers (coalesced 128B per warp instruction)
        float v[32];
        #pragma unroll
        for (int k = 0; k < 32; ++k)
            v[k] = __ldcs(p + k * WX);

        // in-register inclusive prefix over this segment
        #pragma unroll
        for (int k = 1; k < 32; ++k)
            v[k] += v[k - 1];

        // publish segment total, gather carry from lower segments
        seg_totals[seg][lane] = v[31];
        __syncthreads();

        float carry = 0.0f;
        #pragma unroll
        for (int s = 0; s < 15; ++s)
            if (s < seg) carry += seg_totals[s][lane];

        #pragma unroll
        for (int k = 0; k < 32; ++k)
            __stcs(q + k * WX, v[k] + carry);
    } else {
        // ---------------- Channel 0: cumsum along x ----------------
        // warp per 512-float row. lane-contiguous float4 loads:
        // chunk id c = i*32 + lane holds elements [4c, 4c+4).
        const int idx  = bx - CH1_BLOCKS;           // 0..2047
        const int wid  = threadIdx.x >> 5;          // 0..15
        const int lane = threadIdx.x & 31;
        const int row  = idx * 16 + wid;            // 0..32767
        const int b    = row >> 9;
        const int y    = row & 511;

        const int base = ((b * 2 + 0) * WY + y) * WX;
        const float4* __restrict__ src = (const float4*)(in  + base);
        float4*       __restrict__ dst = (float4*)(out + base);

        float4 a0 = __ldcs(src + 0 * 32 + lane);
        float4 a1 = __ldcs(src + 1 * 32 + lane);
        float4 a2 = __ldcs(src + 2 * 32 + lane);
        float4 a3 = __ldcs(src + 3 * 32 + lane);

        // inclusive scan inside each 4-element chunk
        a0.y += a0.x; a0.z += a0.y; a0.w += a0.z;
        a1.y += a1.x; a1.z += a1.y; a1.w += a1.z;
        a2.y += a2.x; a2.z += a2.y; a2.w += a2.z;
        a3.y += a3.x; a3.z += a3.y; a3.w += a3.z;

        // warp scans of chunk totals, one per chunk-row i
        const float t0 = a0.w, t1 = a1.w, t2 = a2.w, t3 = a3.w;
        float i0 = warp_incl_scan(t0, lane);
        float i1 = warp_incl_scan(t1, lane);
        float i2 = warp_incl_scan(t2, lane);
        float i3 = warp_incl_scan(t3, lane);
        const float T0 = __shfl_sync(0xffffffffu, i0, 31);
        const float T1 = __shfl_sync(0xffffffffu, i1, 31);
        const float T2 = __shfl_sync(0xffffffffu, i2, 31);

        // offset for chunk (i, lane) = sum_{j<i} T_j + excl_i(lane)
        const float o0 = i0 - t0;
        const float o1 = (i1 - t1) + T0;
        const float o2 = (i2 - t2) + T0 + T1;
        const float o3 = (i3 - t3) + T0 + T1 + T2;

        a0.x += o0; a0.y += o0; a0.z += o0; a0.w += o0;
        a1.x += o1; a1.y += o1; a1.z += o1; a1.w += o1;
        a2.x += o2; a2.y += o2; a2.z += o2; a2.w += o2;
        a3.x += o3; a3.y += o3; a3.z += o3; a3.w += o3;

        __stcs(dst + 0 * 32 + lane, a0);
        __stcs(dst + 1 * 32 + lane, a1);
        __stcs(dst + 2 * 32 + lane, a2);
        __stcs(dst + 3 * 32 + lane, a3);
    }
}

extern "C" void kernel_launch(void* const* d_in, const int* in_sizes, int n_in,
                              void* d_out, int out_size) {
    const float* in  = (const float*)d_in[0];
    float*       out = (float*)d_out;
    grid_spatial_integral_kernel<<<TOTAL_BLOCKS, THREADS>>>(in, out);
}